// round 7
// baseline (speedup 1.0000x reference)
#include <cuda_runtime.h>
#include <cuda_bf16.h>
#include <math.h>
#include <stdint.h>

#define EPSV 1e-5f
#define BB 2
#define CC 256
#define C8 32
#define NP 4096          // 16*16*16 positions
#define KCONV (CC*27)    // 6912

// ---------------- scratch ----------------
__device__ float g_y[BB*CC*NP];      // conv1 output
__device__ float g_y2[BB*CC*NP];     // conv2 output (separate: conv2 READS g_y)
__device__ float g_out[BB*CC*NP];
__device__ float g_q[BB*C8*NP];
__device__ float g_k[BB*C8*NP];
__device__ float g_v[BB*CC*NP];
__device__ float g_attn[(size_t)BB*NP*NP];           // fp32 energies
__device__ __nv_bfloat16 g_attnh[(size_t)BB*NP*NP];  // bf16 softmaxed attn
__device__ float g_mean[BB*CC];
__device__ float g_rstd[BB*CC];
__device__ float g_wt[CC*KCONV];     // transposed conv weights: wt[co][tap*256+cin]

// unpadded neighbor offsets (strides 256/16/1), tap = (dx+1)*9+(dy+1)*3+(dz+1)
__constant__ int c_udoff[27] = {
  -273,-272,-271,-257,-256,-255,-241,-240,-239,
   -17, -16, -15,  -1,   0,   1,  15,  16,  17,
   239, 240, 241, 255, 256, 257, 271, 272, 273};

// ---------------- helpers ----------------
__device__ __forceinline__ float tf32r(float x) {
    uint32_t u;
    asm("cvt.rna.tf32.f32 %0, %1;" : "=r"(u) : "f"(x));
    return __uint_as_float(u);
}
__device__ __forceinline__ void mma_tf32(float (&d)[4], const float4 &a, const float2 &b) {
    asm volatile(
        "mma.sync.aligned.m16n8k8.row.col.f32.tf32.tf32.f32 "
        "{%0,%1,%2,%3}, {%4,%5,%6,%7}, {%8,%9}, {%0,%1,%2,%3};\n"
        : "+f"(d[0]), "+f"(d[1]), "+f"(d[2]), "+f"(d[3])
        : "r"(__float_as_uint(a.x)), "r"(__float_as_uint(a.y)),
          "r"(__float_as_uint(a.z)), "r"(__float_as_uint(a.w)),
          "r"(__float_as_uint(b.x)), "r"(__float_as_uint(b.y)));
}
__device__ __forceinline__ void mma_bf16(float (&d)[4], const uint4 &a, const uint2 &b) {
    asm volatile(
        "mma.sync.aligned.m16n8k16.row.col.f32.bf16.bf16.f32 "
        "{%0,%1,%2,%3}, {%4,%5,%6,%7}, {%8,%9}, {%0,%1,%2,%3};\n"
        : "+f"(d[0]), "+f"(d[1]), "+f"(d[2]), "+f"(d[3])
        : "r"(a.x), "r"(a.y), "r"(a.z), "r"(a.w), "r"(b.x), "r"(b.y));
}
__device__ __forceinline__ uint32_t pbf2(float lo, float hi) {
    return (uint32_t)__bfloat16_as_ushort(__float2bfloat16_rn(lo))
         | ((uint32_t)__bfloat16_as_ushort(__float2bfloat16_rn(hi)) << 16);
}

// ---------------- weight transpose: wt[co][tap*256+cin] = w[co][cin*27+tap] ----------------
__global__ __launch_bounds__(256) void wtrans_kernel(const float* __restrict__ w) {
    int co = blockIdx.x;
    int cin = threadIdx.x;
    const float* src = w + (size_t)co * KCONV + (size_t)cin * 27;
    float v[27];
    #pragma unroll
    for (int t = 0; t < 27; t++) v[t] = src[t];
    float* dst = g_wt + (size_t)co * KCONV + cin;
    #pragma unroll
    for (int t = 0; t < 27; t++) dst[t * 256] = v[t];
}

// ============================================================================
// Pipelined mma.sync tf32 GEMM, 128x128 tile, k-step 32, 2-stage smem.
// MODE 0, NORM 0 (CONV1): A=g_wt, B=im2col(x via Aext),            dst=g_y
// MODE 0, NORM 1 (CONV2): A=g_wt, B=im2col(instnorm+relu(g_y)),    dst=g_y2
// MODE 1          (VPROJ): A=Aext(wv), B=g_out[c][p],              dst=g_v
// ============================================================================
#define STG_FLOATS 8320
#define SMEM_DYN ((2 * STG_FLOATS + 512) * 4)

template<int MODE, int KTOT, int NORM>
__global__ __launch_bounds__(256, 1)
void tc_gemm(const float* __restrict__ Aext, const float* __restrict__ bias) {
    constexpr int NCH = KTOT / 32;
    extern __shared__ float sm[];
    const int tid = threadIdx.x, wid = tid >> 5, lane = tid & 31;
    const int bb = blockIdx.z;
    const int m0 = blockIdx.y * 128, n0 = blockIdx.x * 128;

    float* smean_ = sm + 2 * STG_FLOATS;
    float* srstd_ = smean_ + 256;
    if (MODE == 0 && NORM) {
        smean_[tid] = g_mean[bb * CC + tid];
        srstd_[tid] = g_rstd[bb * CC + tid];
        __syncthreads();
    }

    // ---- A loader ----
    const int amt = tid >> 5;
    const int arg = (tid >> 2) & 7;
    const int akb = tid & 3;
    const float* aptr0;
    const float* aptr1;
    {
        int m = m0 + amt * 16 + arg;
        const float* base = (MODE == 0) ? g_wt : Aext;
        aptr0 = base + (size_t)m * KTOT + akb * 8;
        aptr1 = base + (size_t)(m + 8) * KTOT + akb * 8;
    }

    // ---- B loader ----
    const int bn = tid >> 1;
    const int bkh = (tid & 1) * 2;
    const float* bbase = nullptr;
    uint32_t pmask = 0;
    if (MODE == 0) {
        int p = n0 + bn;
        int pz = p & 15, py = (p >> 4) & 15, px = p >> 8;
        #pragma unroll
        for (int t = 0; t < 27; t++) {
            int dx = t / 9 - 1, dy = (t / 3) % 3 - 1, dz = t % 3 - 1;
            bool ok = (unsigned)(px + dx) < 16u && (unsigned)(py + dy) < 16u &&
                      (unsigned)(pz + dz) < 16u;
            pmask |= (uint32_t)ok << t;
        }
        const float* src = NORM ? g_y : Aext;   // conv1 reads x via Aext
        bbase = src + (size_t)bb * CC * NP + p;
    } else {
        bbase = g_out + (size_t)bb * CC * NP + n0 + bn;
    }

    float ar0[8], ar1[8], br[16];

    #define LOAD_A(ch_) do { \
        *(float4*)(ar0)     = *(const float4*)(aptr0 + (size_t)(ch_) * 32); \
        *(float4*)(ar0 + 4) = *(const float4*)(aptr0 + (size_t)(ch_) * 32 + 4); \
        *(float4*)(ar1)     = *(const float4*)(aptr1 + (size_t)(ch_) * 32); \
        *(float4*)(ar1 + 4) = *(const float4*)(aptr1 + (size_t)(ch_) * 32 + 4); \
    } while (0)

    #define LOAD_B(ch_) do { \
        if (MODE == 0) { \
            _Pragma("unroll") \
            for (int t = 0; t < 2; t++) { \
                _Pragma("unroll") \
                for (int c = 0; c < 8; c++) { \
                    int k = (ch_) * 32 + (bkh + t) * 8 + c; \
                    int tap = k >> 8, cin = k & 255; \
                    float v = 0.f; \
                    if ((pmask >> tap) & 1u) { \
                        v = bbase[(size_t)cin * NP + c_udoff[tap]]; \
                        if (NORM) v = fmaxf((v - smean_[cin]) * srstd_[cin], 0.f); \
                    } \
                    br[t * 8 + c] = v; \
                } \
            } \
        } else { \
            _Pragma("unroll") \
            for (int t = 0; t < 2; t++) { \
                _Pragma("unroll") \
                for (int c = 0; c < 8; c++) { \
                    int k = (ch_) * 32 + (bkh + t) * 8 + c; \
                    br[t * 8 + c] = bbase[(size_t)k * NP]; \
                } \
            } \
        } \
    } while (0)

    #define STORE_AB(stg_) do { \
        float* As_ = sm + (stg_) * STG_FLOATS + amt * 512 + akb * 128 + arg * 16; \
        _Pragma("unroll") \
        for (int c = 0; c < 4; c++) { \
            *(float4*)(As_ + c * 4) = make_float4( \
                tf32r(ar0[c]), tf32r(ar1[c]), tf32r(ar0[c + 4]), tf32r(ar1[c + 4])); \
        } \
        float* Bs_ = sm + (stg_) * STG_FLOATS + 4096 + (bn >> 3) * 264 + (bn & 7) * 8; \
        _Pragma("unroll") \
        for (int t = 0; t < 2; t++) { \
            int kbb = bkh + t; \
            _Pragma("unroll") \
            for (int c = 0; c < 4; c++) { \
                *(float2*)(Bs_ + kbb * 64 + c * 2) = \
                    make_float2(tf32r(br[t * 8 + c]), tf32r(br[t * 8 + c + 4])); \
            } \
        } \
    } while (0)

    const int wm = wid & 1, wn = wid >> 1;
    float acc[4][4][4];
    #pragma unroll
    for (int i = 0; i < 4; i++)
        #pragma unroll
        for (int j = 0; j < 4; j++)
            #pragma unroll
            for (int k = 0; k < 4; k++) acc[i][j][k] = 0.f;

    // ---- prologue ----
    LOAD_A(0); LOAD_B(0);
    STORE_AB(0);
    LOAD_A(1); LOAD_B(1);
    __syncthreads();

    // ---- mainloop ----
    for (int ch = 0; ch < NCH; ch++) {
        int cur = ch & 1;
        if (ch + 1 < NCH) STORE_AB(cur ^ 1);
        if (ch + 2 < NCH) { LOAD_A(ch + 2); LOAD_B(ch + 2); }

        const float* As_ = sm + cur * STG_FLOATS;
        const float* Bs_ = As_ + 4096;
        #pragma unroll
        for (int kb = 0; kb < 4; kb++) {
            float4 af[4]; float2 bf[4];
            #pragma unroll
            for (int mt = 0; mt < 4; mt++)
                af[mt] = *(const float4*)(As_ + (wm * 4 + mt) * 512 + kb * 128 + lane * 4);
            #pragma unroll
            for (int nt = 0; nt < 4; nt++)
                bf[nt] = *(const float2*)(Bs_ + (wn * 4 + nt) * 264 + kb * 64 + lane * 2);
            #pragma unroll
            for (int mt = 0; mt < 4; mt++)
                #pragma unroll
                for (int nt = 0; nt < 4; nt++)
                    mma_tf32(acc[mt][nt], af[mt], bf[nt]);
        }
        __syncthreads();
    }

    #undef LOAD_A
    #undef LOAD_B
    #undef STORE_AB

    // ---- epilogue ----
    const int g = lane >> 2, tg = lane & 3;
    // dst resolved in device code: conv1->g_y, conv2->g_y2 (conv2 READS g_y!), vproj->g_v
    float* dst = (MODE == 1) ? g_v : (NORM ? g_y2 : g_y);
    #pragma unroll
    for (int mt = 0; mt < 4; mt++) {
        int m = m0 + wm * 64 + mt * 16 + g;
        float bs0 = bias[m], bs1 = bias[m + 8];
        #pragma unroll
        for (int nt = 0; nt < 4; nt++) {
            int n = n0 + wn * 32 + nt * 8 + tg * 2;
            size_t base0 = (size_t)(bb * CC + m) * NP + n;
            size_t base1 = base0 + (size_t)8 * NP;
            *(float2*)(dst + base0) = make_float2(acc[mt][nt][0] + bs0, acc[mt][nt][1] + bs0);
            *(float2*)(dst + base1) = make_float2(acc[mt][nt][2] + bs1, acc[mt][nt][3] + bs1);
        }
    }
}

// ============================================================================
// o-GEMM, bf16 m16n8k16: o[c,i] = sum_j v[c,j]*attnh[i,j]; dout = gamma*o+g_out
// ============================================================================
#define OA_U32 2048
#define OB_U32 (16*136)
#define OSTG_U32 (OA_U32 + OB_U32)
#define OSMEM (2 * OSTG_U32 * 4)

__global__ __launch_bounds__(256, 1)
void o_gemm_bf16(const float* __restrict__ gamma, float* __restrict__ dout) {
    extern __shared__ uint32_t smu[];
    const int tid = threadIdx.x, wid = tid >> 5, lane = tid & 31;
    const int bb = blockIdx.z, m0 = blockIdx.y * 128, i0 = blockIdx.x * 128;
    const int wm = wid & 1, wn = wid >> 1;

    const float *av0 = nullptr, *av1 = nullptr;
    uint32_t aoff = 0;
    if (tid < 128) {
        int rpi = tid >> 1, akb = tid & 1;
        int mt = rpi >> 3, rp = rpi & 7;
        int m = m0 + mt * 16 + rp;
        av0 = g_v + (size_t)(bb * CC + m) * NP + akb * 16;
        av1 = av0 + (size_t)8 * NP;
        aoff = mt * 256 + akb * 128 + rp * 16;
    }
    const int bn = tid >> 1, bkb = tid & 1;
    const __nv_bfloat16* bptr = g_attnh + ((size_t)bb * NP + i0 + bn) * NP + bkb * 16;
    const uint32_t boff = OA_U32 + (bn >> 3) * 136 + bkb * 68 + (bn & 7) * 8;

    float a0r[16], a1r[16];
    uint32_t brg[8];

    #define OLOAD(ch_) do { \
        if (tid < 128) { \
            _Pragma("unroll") \
            for (int q = 0; q < 4; q++) { \
                *(float4*)(a0r + q * 4) = *(const float4*)(av0 + (size_t)(ch_) * 32 + q * 4); \
                *(float4*)(a1r + q * 4) = *(const float4*)(av1 + (size_t)(ch_) * 32 + q * 4); \
            } \
        } \
        *(uint4*)(brg)     = *(const uint4*)(bptr + (size_t)(ch_) * 32); \
        *(uint4*)(brg + 4) = *(const uint4*)(bptr + (size_t)(ch_) * 32 + 8); \
    } while (0)

    #define OSTORE(stg_) do { \
        uint32_t* s_ = smu + (stg_) * OSTG_U32; \
        if (tid < 128) { \
            _Pragma("unroll") \
            for (int t = 0; t < 4; t++) { \
                uint4 w; \
                w.x = pbf2(a0r[2 * t],     a0r[2 * t + 1]); \
                w.y = pbf2(a1r[2 * t],     a1r[2 * t + 1]); \
                w.z = pbf2(a0r[2 * t + 8], a0r[2 * t + 9]); \
                w.w = pbf2(a1r[2 * t + 8], a1r[2 * t + 9]); \
                *(uint4*)(s_ + aoff + t * 4) = w; \
            } \
        } \
        _Pragma("unroll") \
        for (int t = 0; t < 4; t++) \
            *(uint2*)(s_ + boff + t * 2) = make_uint2(brg[t], brg[t + 4]); \
    } while (0)

    float acc[4][4][4];
    #pragma unroll
    for (int i = 0; i < 4; i++)
        #pragma unroll
        for (int j = 0; j < 4; j++)
            #pragma unroll
            for (int k = 0; k < 4; k++) acc[i][j][k] = 0.f;

    OLOAD(0); OSTORE(0); OLOAD(1);
    __syncthreads();

    constexpr int NCH = NP / 32;   // 128
    for (int ch = 0; ch < NCH; ch++) {
        int cur = ch & 1;
        if (ch + 1 < NCH) OSTORE(cur ^ 1);
        if (ch + 2 < NCH) OLOAD(ch + 2);

        const uint32_t* s_ = smu + cur * OSTG_U32;
        #pragma unroll
        for (int kb = 0; kb < 2; kb++) {
            uint4 af[4]; uint2 bf[4];
            #pragma unroll
            for (int mt = 0; mt < 4; mt++)
                af[mt] = *(const uint4*)(s_ + (wm * 4 + mt) * 256 + kb * 128 + lane * 4);
            #pragma unroll
            for (int nt = 0; nt < 4; nt++)
                bf[nt] = *(const uint2*)(s_ + OA_U32 + (wn * 4 + nt) * 136 + kb * 68 + lane * 2);
            #pragma unroll
            for (int mt = 0; mt < 4; mt++)
                #pragma unroll
                for (int nt = 0; nt < 4; nt++)
                    mma_bf16(acc[mt][nt], af[mt], bf[nt]);
        }
        __syncthreads();
    }

    #undef OLOAD
    #undef OSTORE

    const int g = lane >> 2, tg = lane & 3;
    const float gm = gamma[0];
    #pragma unroll
    for (int mt = 0; mt < 4; mt++) {
        int m = m0 + wm * 64 + mt * 16 + g;
        #pragma unroll
        for (int nt = 0; nt < 4; nt++) {
            int n = i0 + wn * 32 + nt * 8 + tg * 2;
            size_t base0 = (size_t)(bb * CC + m) * NP + n;
            size_t base1 = base0 + (size_t)8 * NP;
            const float* r0 = g_out + base0;
            const float* r1 = g_out + base1;
            *(float2*)(dout + base0) =
                make_float2(gm * acc[mt][nt][0] + r0[0], gm * acc[mt][nt][1] + r0[1]);
            *(float2*)(dout + base1) =
                make_float2(gm * acc[mt][nt][2] + r1[0], gm * acc[mt][nt][3] + r1[1]);
        }
    }
}

// ---------------- stats: which=0 -> g_y, which=1 -> g_y2 ----------------
__global__ void stats_kernel(int which) {
    int bc = blockIdx.x;
    const float* src = (which ? g_y2 : g_y) + (size_t)bc * NP;
    float s = 0.f, ss = 0.f;
    for (int i = threadIdx.x; i < NP; i += 256) {
        float v = src[i]; s += v; ss += v * v;
    }
    #pragma unroll
    for (int o = 16; o; o >>= 1) {
        s  += __shfl_down_sync(0xffffffffu, s, o);
        ss += __shfl_down_sync(0xffffffffu, ss, o);
    }
    __shared__ float sh_s[8], sh_ss[8];
    int w = threadIdx.x >> 5, l = threadIdx.x & 31;
    if (l == 0) { sh_s[w] = s; sh_ss[w] = ss; }
    __syncthreads();
    if (threadIdx.x == 0) {
        float S = 0.f, SS = 0.f;
        #pragma unroll
        for (int i = 0; i < 8; i++) { S += sh_s[i]; SS += sh_ss[i]; }
        float m = S * (1.0f / NP);
        float var = SS * (1.0f / NP) - m * m;
        g_mean[bc] = m;
        g_rstd[bc] = rsqrtf(var + EPSV);
    }
}

// ---------------- out = x + instnorm(g_y2) ----------------
__global__ void norm_add_kernel(const float* __restrict__ x) {
    int idx = blockIdx.x * 256 + threadIdx.x;
    int bc = idx >> 12;
    float m = g_mean[bc], r = g_rstd[bc];
    g_out[idx] = x[idx] + (g_y2[idx] - m) * r;
}

// ---------------- energy: energy[b,i,j] = sum_c q[b,c,i]*k[b,c,j], K=32 ----------------
__global__ __launch_bounds__(256) void energy_tc() {
    __shared__ float As[8][2][32][4];
    __shared__ float Bs[16][2][32][2];
    int tid = threadIdx.x, b = blockIdx.z;
    int i0 = blockIdx.y * 128, j0 = blockIdx.x * 128;

    int cl = tid >> 4, ig = tid & 15;
    int ckblk = cl >> 3, ckc = cl & 7;

    int wid = tid >> 5, lane = tid & 31;
    int wm = wid & 1, wn = wid >> 1;

    float acc[4][4][4];
    #pragma unroll
    for (int i = 0; i < 4; i++)
        #pragma unroll
        for (int j = 0; j < 4; j++)
            #pragma unroll
            for (int k = 0; k < 4; k++) acc[i][j][k] = 0.f;

    #pragma unroll
    for (int it = 0; it < 2; ++it) {
        int c = it * 16 + cl;
        const float* qsrc = g_q + (size_t)(b * C8 + c) * NP + i0 + ig * 8;
        const float* ksrc = g_k + (size_t)(b * C8 + c) * NP + j0 + ig * 8;
        float4 q0 = *(const float4*)qsrc, q1 = *(const float4*)(qsrc + 4);
        float4 k0 = *(const float4*)ksrc, k1 = *(const float4*)(ksrc + 4);

        __syncthreads();
        {
            float qv[8] = {q0.x, q0.y, q0.z, q0.w, q1.x, q1.y, q1.z, q1.w};
            #pragma unroll
            for (int ii = 0; ii < 8; ii++) {
                int r = ig * 8 + ii;
                int mtile = r >> 4, rr = r & 15;
                As[mtile][ckblk][(rr & 7) * 4 + (ckc & 3)][(rr >> 3) + ((ckc >> 2) << 1)] = tf32r(qv[ii]);
            }
            float kv[8] = {k0.x, k0.y, k0.z, k0.w, k1.x, k1.y, k1.z, k1.w};
            #pragma unroll
            for (int nn = 0; nn < 8; nn++)
                Bs[ig][ckblk][nn * 4 + (ckc & 3)][ckc >> 2] = tf32r(kv[nn]);
        }
        __syncthreads();

        #pragma unroll
        for (int kb = 0; kb < 2; kb++) {
            float4 af[4]; float2 bf[4];
            #pragma unroll
            for (int mt = 0; mt < 4; mt++) af[mt] = *(const float4*)As[wm * 4 + mt][kb][lane];
            #pragma unroll
            for (int nt = 0; nt < 4; nt++) bf[nt] = *(const float2*)Bs[wn * 4 + nt][kb][lane];
            #pragma unroll
            for (int mt = 0; mt < 4; mt++)
                #pragma unroll
                for (int nt = 0; nt < 4; nt++)
                    mma_tf32(acc[mt][nt], af[mt], bf[nt]);
        }
    }

    int g = lane >> 2, tg = lane & 3;
    #pragma unroll
    for (int mt = 0; mt < 4; mt++) {
        int m = i0 + wm * 64 + mt * 16 + g;
        #pragma unroll
        for (int nt = 0; nt < 4; nt++) {
            int n = j0 + wn * 32 + nt * 8 + tg * 2;
            float* d0 = g_attn + ((size_t)b * NP + m) * NP + n;
            *(float2*)d0 = make_float2(acc[mt][nt][0], acc[mt][nt][1]);
            *(float2*)(d0 + (size_t)8 * NP) = make_float2(acc[mt][nt][2], acc[mt][nt][3]);
        }
    }
}

// ---------------- q and k projections fused (FFMA, small) ----------------
__global__ __launch_bounds__(256) void qk_gemm(const float* __restrict__ wq, const float* __restrict__ bq,
                                               const float* __restrict__ wk, const float* __restrict__ bk) {
    __shared__ float As[8][64];
    __shared__ float Bs[8][128];
    int tid = threadIdx.x, b = blockIdx.z;
    int p0 = blockIdx.x * 128;
    int arow = tid >> 2;
    int acol = (tid & 3) * 2;
    const float* ap = ((arow < 32) ? (wq + arow * CC) : (wk + (arow - 32) * CC)) + acol;
    int brow = tid >> 5, bcol = (tid & 31) * 4;
    const float* bp = g_out + (b * CC + brow) * NP + p0 + bcol;
    int ty = tid >> 4, tx = tid & 15;
    float acc[4][8];
    #pragma unroll
    for (int i = 0; i < 4; i++)
        #pragma unroll
        for (int j = 0; j < 8; j++) acc[i][j] = 0.f;

    for (int it = 0; it < CC / 8; ++it) {
        float2 av = *(const float2*)(ap + it * 8);
        float4 bv = *(const float4*)(bp + (size_t)it * 8 * NP);
        __syncthreads();
        As[acol + 0][arow] = av.x;
        As[acol + 1][arow] = av.y;
        *(float4*)&Bs[brow][bcol] = bv;
        __syncthreads();
        #pragma unroll
        for (int kk = 0; kk < 8; kk++) {
            float a[4], bvv[8];
            float4 t0 = *(const float4*)&As[kk][ty * 4];
            a[0]=t0.x; a[1]=t0.y; a[2]=t0.z; a[3]=t0.w;
            float4 u0 = *(const float4*)&Bs[kk][tx * 8];
            float4 u1 = *(const float4*)&Bs[kk][tx * 8 + 4];
            bvv[0]=u0.x; bvv[1]=u0.y; bvv[2]=u0.z; bvv[3]=u0.w;
            bvv[4]=u1.x; bvv[5]=u1.y; bvv[6]=u1.z; bvv[7]=u1.w;
            #pragma unroll
            for (int i = 0; i < 4; i++)
                #pragma unroll
                for (int j = 0; j < 8; j++)
                    acc[i][j] += a[i] * bvv[j];
        }
    }
    #pragma unroll
    for (int i = 0; i < 4; i++) {
        int row = ty * 4 + i;
        float bias = (row < 32) ? bq[row] : bk[row - 32];
        float* dst = ((row < 32) ? (g_q + (b * C8 + row) * NP)
                                 : (g_k + (b * C8 + row - 32) * NP)) + p0 + tx * 8;
        *(float4*)dst       = make_float4(acc[i][0]+bias, acc[i][1]+bias, acc[i][2]+bias, acc[i][3]+bias);
        *(float4*)(dst + 4) = make_float4(acc[i][4]+bias, acc[i][5]+bias, acc[i][6]+bias, acc[i][7]+bias);
    }
}

// ---------------- row softmax over 4096: fp32 in -> bf16 out ----------------
__global__ __launch_bounds__(256) void softmax_kernel() {
    size_t row = blockIdx.x;
    const float* ptr = g_attn + row * (size_t)NP;
    __nv_bfloat16* op = g_attnh + row * (size_t)NP;
    int tid = threadIdx.x;
    float vals[16];
    float m = -1e30f;
    #pragma unroll
    for (int s = 0; s < 16; s++) {
        vals[s] = ptr[tid + s * 256];
        m = fmaxf(m, vals[s]);
    }
    #pragma unroll
    for (int o = 16; o; o >>= 1) m = fmaxf(m, __shfl_xor_sync(0xffffffffu, m, o));
    __shared__ float shm[8], shs[8];
    int w = tid >> 5, l = tid & 31;
    if (l == 0) shm[w] = m;
    __syncthreads();
    m = fmaxf(fmaxf(fmaxf(shm[0], shm[1]), fmaxf(shm[2], shm[3])),
              fmaxf(fmaxf(shm[4], shm[5]), fmaxf(shm[6], shm[7])));
    float sum = 0.f;
    #pragma unroll
    for (int s = 0; s < 16; s++) {
        vals[s] = __expf(vals[s] - m);
        sum += vals[s];
    }
    #pragma unroll
    for (int o = 16; o; o >>= 1) sum += __shfl_xor_sync(0xffffffffu, sum, o);
    if (l == 0) shs[w] = sum;
    __syncthreads();
    sum = shs[0] + shs[1] + shs[2] + shs[3] + shs[4] + shs[5] + shs[6] + shs[7];
    float inv = 1.0f / sum;
    #pragma unroll
    for (int s = 0; s < 16; s++)
        op[tid + s * 256] = __float2bfloat16_rn(vals[s] * inv);
}

// ---------------- launcher ----------------
extern "C" void kernel_launch(void* const* d_in, const int* in_sizes, int n_in,
                              void* d_out, int out_size) {
    const float* x     = (const float*)d_in[0];
    const float* w1    = (const float*)d_in[1];
    const float* b1    = (const float*)d_in[2];
    const float* w2    = (const float*)d_in[3];
    const float* b2    = (const float*)d_in[4];
    const float* wq    = (const float*)d_in[5];
    const float* bq    = (const float*)d_in[6];
    const float* wk    = (const float*)d_in[7];
    const float* bk    = (const float*)d_in[8];
    const float* wv    = (const float*)d_in[9];
    const float* bv    = (const float*)d_in[10];
    const float* gamma = (const float*)d_in[11];
    float* out = (float*)d_out;

    cudaFuncSetAttribute(tc_gemm<0, KCONV, 0>, cudaFuncAttributeMaxDynamicSharedMemorySize, SMEM_DYN);
    cudaFuncSetAttribute(tc_gemm<0, KCONV, 1>, cudaFuncAttributeMaxDynamicSharedMemorySize, SMEM_DYN);
    cudaFuncSetAttribute(tc_gemm<1, CC, 0>,    cudaFuncAttributeMaxDynamicSharedMemorySize, SMEM_DYN);
    cudaFuncSetAttribute(o_gemm_bf16,          cudaFuncAttributeMaxDynamicSharedMemorySize, OSMEM);

    dim3 g128(NP / 128, CC / 128, BB);   // (32,2,2)

    // conv block (pad + norm fused into conv B-loader; conv2 dst = g_y2)
    wtrans_kernel<<<CC, 256>>>(w1);
    tc_gemm<0, KCONV, 0><<<g128, 256, SMEM_DYN>>>(x, b1);
    stats_kernel<<<BB * CC, 256>>>(0);
    wtrans_kernel<<<CC, 256>>>(w2);
    tc_gemm<0, KCONV, 1><<<g128, 256, SMEM_DYN>>>(nullptr, b2);
    stats_kernel<<<BB * CC, 256>>>(1);
    norm_add_kernel<<<BB * CC * NP / 256, 256>>>(x);

    // attention
    qk_gemm<<<dim3(NP / 128, 1, BB), 256>>>(wq, bq, wk, bk);
    tc_gemm<1, CC, 0><<<g128, 256, SMEM_DYN>>>(wv, bv);
    energy_tc<<<dim3(NP / 128, NP / 128, BB), 256>>>();
    softmax_kernel<<<BB * NP, 256>>>();
    o_gemm_bf16<<<g128, 256, OSMEM>>>(gamma, out);
}

// round 8
// speedup vs baseline: 1.1503x; 1.1503x over previous
#include <cuda_runtime.h>
#include <cuda_bf16.h>
#include <math.h>
#include <stdint.h>

#define EPSV 1e-5f
#define BB 2
#define CC 256
#define C8 32
#define NP 4096          // 16*16*16 positions
#define PADN 5832        // 18*18*18
#define KCONV (CC*27)    // 6912

// ---------------- scratch ----------------
__device__ float g_pad[BB*CC*PADN];
__device__ float g_y[BB*CC*NP];
__device__ float g_out[BB*CC*NP];
__device__ float g_q[BB*C8*NP];
__device__ float g_k[BB*C8*NP];
__device__ float g_v[BB*CC*NP];
__device__ float g_attn[(size_t)BB*NP*NP];           // fp32 energies
__device__ __nv_bfloat16 g_attnh[(size_t)BB*NP*NP];  // bf16 softmaxed attn
__device__ float g_mean[BB*CC];
__device__ float g_rstd[BB*CC];
__device__ float g_wt[CC*KCONV];     // transposed conv weights: wt[co][tap*256+cin]

// padded-offset per conv tap (strides 324/18/1)
__constant__ int c_doff[27] = {
  -343,-342,-341,-325,-324,-323,-307,-306,-305,
   -19, -18, -17,  -1,   0,   1,  17,  18,  19,
   305, 306, 307, 323, 324, 325, 341, 342, 343};

// ---------------- helpers ----------------
__device__ __forceinline__ float tf32r(float x) {
    uint32_t u;
    asm("cvt.rna.tf32.f32 %0, %1;" : "=r"(u) : "f"(x));
    return __uint_as_float(u);
}
__device__ __forceinline__ void mma_tf32(float (&d)[4], const float4 &a, const float2 &b) {
    asm volatile(
        "mma.sync.aligned.m16n8k8.row.col.f32.tf32.tf32.f32 "
        "{%0,%1,%2,%3}, {%4,%5,%6,%7}, {%8,%9}, {%0,%1,%2,%3};\n"
        : "+f"(d[0]), "+f"(d[1]), "+f"(d[2]), "+f"(d[3])
        : "r"(__float_as_uint(a.x)), "r"(__float_as_uint(a.y)),
          "r"(__float_as_uint(a.z)), "r"(__float_as_uint(a.w)),
          "r"(__float_as_uint(b.x)), "r"(__float_as_uint(b.y)));
}
__device__ __forceinline__ void mma_bf16(float (&d)[4], const uint4 &a, const uint2 &b) {
    asm volatile(
        "mma.sync.aligned.m16n8k16.row.col.f32.bf16.bf16.f32 "
        "{%0,%1,%2,%3}, {%4,%5,%6,%7}, {%8,%9}, {%0,%1,%2,%3};\n"
        : "+f"(d[0]), "+f"(d[1]), "+f"(d[2]), "+f"(d[3])
        : "r"(a.x), "r"(a.y), "r"(a.z), "r"(a.w), "r"(b.x), "r"(b.y));
}
__device__ __forceinline__ uint32_t pbf2(float lo, float hi) {
    return (uint32_t)__bfloat16_as_ushort(__float2bfloat16_rn(lo))
         | ((uint32_t)__bfloat16_as_ushort(__float2bfloat16_rn(hi)) << 16);
}

// ---------------- weight transpose: wt[co][tap*256+cin] = w[co][cin*27+tap] ----------------
__global__ __launch_bounds__(256) void wtrans_kernel(const float* __restrict__ w) {
    int co = blockIdx.x;
    int cin = threadIdx.x;
    const float* src = w + (size_t)co * KCONV + (size_t)cin * 27;
    float v[27];
    #pragma unroll
    for (int t = 0; t < 27; t++) v[t] = src[t];
    float* dst = g_wt + (size_t)co * KCONV + cin;
    #pragma unroll
    for (int t = 0; t < 27; t++) dst[t * 256] = v[t];
}

// ---------------- pad kernel: mode 0: x -> g_pad ; mode 1: instnorm+relu(g_y) -> g_pad
__global__ void pad_kernel(const float* __restrict__ x, int mode) {
    int bc = blockIdx.x;
    const float* src = (mode == 0) ? (x + bc * NP) : (g_y + bc * NP);
    float m = 0.f, r = 1.f;
    if (mode == 1) { m = g_mean[bc]; r = g_rstd[bc]; }
    float* dst = g_pad + bc * PADN;
    for (int i = threadIdx.x; i < PADN; i += blockDim.x) {
        int zp = i % 18; int t = i / 18; int yp = t % 18; int xp = t / 18;
        float v = 0.f;
        if (xp >= 1 && xp <= 16 && yp >= 1 && yp <= 16 && zp >= 1 && zp <= 16) {
            v = src[(xp - 1) * 256 + (yp - 1) * 16 + (zp - 1)];
            if (mode == 1) { v = (v - m) * r; v = v > 0.f ? v : 0.f; }
        }
        dst[i] = v;
    }
}

// ============================================================================
// Pipelined mma.sync tf32 GEMM, 128x128 tile, k-step 32, 2-stage smem.
// MODE 0 (CONV):  A=g_wt[co][(tap,cin)], B=im2col(g_pad), dst=g_y (+bias)
// MODE 1 (VPROJ): A=Aext(wv),            B=g_out[c][p],   dst=g_v (+bias)
// ============================================================================
#define STG_FLOATS 8320
#define SMEM_DYN (2 * STG_FLOATS * 4)

template<int MODE, int KTOT>
__global__ __launch_bounds__(256, 1)
void tc_gemm(const float* __restrict__ Aext, const float* __restrict__ bias) {
    constexpr int NCH = KTOT / 32;
    extern __shared__ float sm[];
    const int tid = threadIdx.x, wid = tid >> 5, lane = tid & 31;
    const int bb = blockIdx.z;
    const int m0 = blockIdx.y * 128, n0 = blockIdx.x * 128;

    // ---- A loader ----
    const int amt = tid >> 5;
    const int arg = (tid >> 2) & 7;
    const int akb = tid & 3;
    const float* aptr0;
    const float* aptr1;
    {
        int m = m0 + amt * 16 + arg;
        const float* base = (MODE == 0) ? g_wt : Aext;
        aptr0 = base + (size_t)m * KTOT + akb * 8;
        aptr1 = base + (size_t)(m + 8) * KTOT + akb * 8;
    }

    // ---- B loader ----
    const int bn = tid >> 1;
    const int bkh = (tid & 1) * 2;
    int pofs = 0;
    const float* bbase = nullptr;
    if (MODE == 0) {
        int p = n0 + bn;
        int pz = p & 15, py = (p >> 4) & 15, px = p >> 8;
        pofs = (px + 1) * 324 + (py + 1) * 18 + (pz + 1);
        bbase = g_pad + (size_t)bb * CC * PADN;
    } else {
        bbase = g_out + (size_t)bb * CC * NP + n0 + bn;
    }

    float ar0[8], ar1[8], br[16];

    #define LOAD_A(ch_) do { \
        *(float4*)(ar0)     = *(const float4*)(aptr0 + (size_t)(ch_) * 32); \
        *(float4*)(ar0 + 4) = *(const float4*)(aptr0 + (size_t)(ch_) * 32 + 4); \
        *(float4*)(ar1)     = *(const float4*)(aptr1 + (size_t)(ch_) * 32); \
        *(float4*)(ar1 + 4) = *(const float4*)(aptr1 + (size_t)(ch_) * 32 + 4); \
    } while (0)

    #define LOAD_B(ch_) do { \
        if (MODE == 0) { \
            _Pragma("unroll") \
            for (int t = 0; t < 2; t++) { \
                _Pragma("unroll") \
                for (int c = 0; c < 8; c++) { \
                    int k = (ch_) * 32 + (bkh + t) * 8 + c; \
                    int tap = k >> 8, cin = k & 255; \
                    br[t * 8 + c] = bbase[(size_t)cin * PADN + c_doff[tap] + pofs]; \
                } \
            } \
        } else { \
            _Pragma("unroll") \
            for (int t = 0; t < 2; t++) { \
                _Pragma("unroll") \
                for (int c = 0; c < 8; c++) { \
                    int k = (ch_) * 32 + (bkh + t) * 8 + c; \
                    br[t * 8 + c] = bbase[(size_t)k * NP]; \
                } \
            } \
        } \
    } while (0)

    #define STORE_AB(stg_) do { \
        float* As_ = sm + (stg_) * STG_FLOATS + amt * 512 + akb * 128 + arg * 16; \
        _Pragma("unroll") \
        for (int c = 0; c < 4; c++) { \
            *(float4*)(As_ + c * 4) = make_float4( \
                tf32r(ar0[c]), tf32r(ar1[c]), tf32r(ar0[c + 4]), tf32r(ar1[c + 4])); \
        } \
        float* Bs_ = sm + (stg_) * STG_FLOATS + 4096 + (bn >> 3) * 264 + (bn & 7) * 8; \
        _Pragma("unroll") \
        for (int t = 0; t < 2; t++) { \
            int kbb = bkh + t; \
            _Pragma("unroll") \
            for (int c = 0; c < 4; c++) { \
                *(float2*)(Bs_ + kbb * 64 + c * 2) = \
                    make_float2(tf32r(br[t * 8 + c]), tf32r(br[t * 8 + c + 4])); \
            } \
        } \
    } while (0)

    const int wm = wid & 1, wn = wid >> 1;
    float acc[4][4][4];
    #pragma unroll
    for (int i = 0; i < 4; i++)
        #pragma unroll
        for (int j = 0; j < 4; j++)
            #pragma unroll
            for (int k = 0; k < 4; k++) acc[i][j][k] = 0.f;

    // ---- prologue ----
    LOAD_A(0); LOAD_B(0);
    STORE_AB(0);
    LOAD_A(1); LOAD_B(1);
    __syncthreads();

    // ---- mainloop ----
    for (int ch = 0; ch < NCH; ch++) {
        int cur = ch & 1;
        if (ch + 1 < NCH) STORE_AB(cur ^ 1);
        if (ch + 2 < NCH) { LOAD_A(ch + 2); LOAD_B(ch + 2); }

        const float* As_ = sm + cur * STG_FLOATS;
        const float* Bs_ = As_ + 4096;
        #pragma unroll
        for (int kb = 0; kb < 4; kb++) {
            float4 af[4]; float2 bf[4];
            #pragma unroll
            for (int mt = 0; mt < 4; mt++)
                af[mt] = *(const float4*)(As_ + (wm * 4 + mt) * 512 + kb * 128 + lane * 4);
            #pragma unroll
            for (int nt = 0; nt < 4; nt++)
                bf[nt] = *(const float2*)(Bs_ + (wn * 4 + nt) * 264 + kb * 64 + lane * 2);
            #pragma unroll
            for (int mt = 0; mt < 4; mt++)
                #pragma unroll
                for (int nt = 0; nt < 4; nt++)
                    mma_tf32(acc[mt][nt], af[mt], bf[nt]);
        }
        __syncthreads();
    }

    #undef LOAD_A
    #undef LOAD_B
    #undef STORE_AB

    // ---- epilogue ----
    const int g = lane >> 2, tg = lane & 3;
    float* dst = (MODE == 0) ? g_y : g_v;
    #pragma unroll
    for (int mt = 0; mt < 4; mt++) {
        int m = m0 + wm * 64 + mt * 16 + g;
        float bs0 = bias[m], bs1 = bias[m + 8];
        #pragma unroll
        for (int nt = 0; nt < 4; nt++) {
            int n = n0 + wn * 32 + nt * 8 + tg * 2;
            size_t base0 = (size_t)(bb * CC + m) * NP + n;
            size_t base1 = base0 + (size_t)8 * NP;
            *(float2*)(dst + base0) = make_float2(acc[mt][nt][0] + bs0, acc[mt][nt][1] + bs0);
            *(float2*)(dst + base1) = make_float2(acc[mt][nt][2] + bs1, acc[mt][nt][3] + bs1);
        }
    }
}

// ============================================================================
// o-GEMM, bf16 m16n8k16: o[c,i] = sum_j v[c,j]*attnh[i,j]; dout = gamma*o+g_out
// ============================================================================
#define OA_U32 2048
#define OB_U32 (16*136)
#define OSTG_U32 (OA_U32 + OB_U32)
#define OSMEM (2 * OSTG_U32 * 4)

__global__ __launch_bounds__(256, 1)
void o_gemm_bf16(const float* __restrict__ gamma, float* __restrict__ dout) {
    extern __shared__ uint32_t smu[];
    const int tid = threadIdx.x, wid = tid >> 5, lane = tid & 31;
    const int bb = blockIdx.z, m0 = blockIdx.y * 128, i0 = blockIdx.x * 128;
    const int wm = wid & 1, wn = wid >> 1;

    const float *av0 = nullptr, *av1 = nullptr;
    uint32_t aoff = 0;
    if (tid < 128) {
        int rpi = tid >> 1, akb = tid & 1;
        int mt = rpi >> 3, rp = rpi & 7;
        int m = m0 + mt * 16 + rp;
        av0 = g_v + (size_t)(bb * CC + m) * NP + akb * 16;
        av1 = av0 + (size_t)8 * NP;
        aoff = mt * 256 + akb * 128 + rp * 16;
    }
    const int bn = tid >> 1, bkb = tid & 1;
    const __nv_bfloat16* bptr = g_attnh + ((size_t)bb * NP + i0 + bn) * NP + bkb * 16;
    const uint32_t boff = OA_U32 + (bn >> 3) * 136 + bkb * 68 + (bn & 7) * 8;

    float a0r[16], a1r[16];
    uint32_t brg[8];

    #define OLOAD(ch_) do { \
        if (tid < 128) { \
            _Pragma("unroll") \
            for (int q = 0; q < 4; q++) { \
                *(float4*)(a0r + q * 4) = *(const float4*)(av0 + (size_t)(ch_) * 32 + q * 4); \
                *(float4*)(a1r + q * 4) = *(const float4*)(av1 + (size_t)(ch_) * 32 + q * 4); \
            } \
        } \
        *(uint4*)(brg)     = *(const uint4*)(bptr + (size_t)(ch_) * 32); \
        *(uint4*)(brg + 4) = *(const uint4*)(bptr + (size_t)(ch_) * 32 + 8); \
    } while (0)

    #define OSTORE(stg_) do { \
        uint32_t* s_ = smu + (stg_) * OSTG_U32; \
        if (tid < 128) { \
            _Pragma("unroll") \
            for (int t = 0; t < 4; t++) { \
                uint4 w; \
                w.x = pbf2(a0r[2 * t],     a0r[2 * t + 1]); \
                w.y = pbf2(a1r[2 * t],     a1r[2 * t + 1]); \
                w.z = pbf2(a0r[2 * t + 8], a0r[2 * t + 9]); \
                w.w = pbf2(a1r[2 * t + 8], a1r[2 * t + 9]); \
                *(uint4*)(s_ + aoff + t * 4) = w; \
            } \
        } \
        _Pragma("unroll") \
        for (int t = 0; t < 4; t++) \
            *(uint2*)(s_ + boff + t * 2) = make_uint2(brg[t], brg[t + 4]); \
    } while (0)

    float acc[4][4][4];
    #pragma unroll
    for (int i = 0; i < 4; i++)
        #pragma unroll
        for (int j = 0; j < 4; j++)
            #pragma unroll
            for (int k = 0; k < 4; k++) acc[i][j][k] = 0.f;

    OLOAD(0); OSTORE(0); OLOAD(1);
    __syncthreads();

    constexpr int NCH = NP / 32;   // 128
    for (int ch = 0; ch < NCH; ch++) {
        int cur = ch & 1;
        if (ch + 1 < NCH) OSTORE(cur ^ 1);
        if (ch + 2 < NCH) OLOAD(ch + 2);

        const uint32_t* s_ = smu + cur * OSTG_U32;
        #pragma unroll
        for (int kb = 0; kb < 2; kb++) {
            uint4 af[4]; uint2 bf[4];
            #pragma unroll
            for (int mt = 0; mt < 4; mt++)
                af[mt] = *(const uint4*)(s_ + (wm * 4 + mt) * 256 + kb * 128 + lane * 4);
            #pragma unroll
            for (int nt = 0; nt < 4; nt++)
                bf[nt] = *(const uint2*)(s_ + OA_U32 + (wn * 4 + nt) * 136 + kb * 68 + lane * 2);
            #pragma unroll
            for (int mt = 0; mt < 4; mt++)
                #pragma unroll
                for (int nt = 0; nt < 4; nt++)
                    mma_bf16(acc[mt][nt], af[mt], bf[nt]);
        }
        __syncthreads();
    }

    #undef OLOAD
    #undef OSTORE

    const int g = lane >> 2, tg = lane & 3;
    const float gm = gamma[0];
    #pragma unroll
    for (int mt = 0; mt < 4; mt++) {
        int m = m0 + wm * 64 + mt * 16 + g;
        #pragma unroll
        for (int nt = 0; nt < 4; nt++) {
            int n = i0 + wn * 32 + nt * 8 + tg * 2;
            size_t base0 = (size_t)(bb * CC + m) * NP + n;
            size_t base1 = base0 + (size_t)8 * NP;
            const float* r0 = g_out + base0;
            const float* r1 = g_out + base1;
            *(float2*)(dout + base0) =
                make_float2(gm * acc[mt][nt][0] + r0[0], gm * acc[mt][nt][1] + r0[1]);
            *(float2*)(dout + base1) =
                make_float2(gm * acc[mt][nt][2] + r1[0], gm * acc[mt][nt][3] + r1[1]);
        }
    }
}

// ---------------- stats (reads g_y) ----------------
__global__ void stats_kernel() {
    int bc = blockIdx.x;
    const float* src = g_y + (size_t)bc * NP;
    float s = 0.f, ss = 0.f;
    for (int i = threadIdx.x; i < NP; i += 256) {
        float v = src[i]; s += v; ss += v * v;
    }
    #pragma unroll
    for (int o = 16; o; o >>= 1) {
        s  += __shfl_down_sync(0xffffffffu, s, o);
        ss += __shfl_down_sync(0xffffffffu, ss, o);
    }
    __shared__ float sh_s[8], sh_ss[8];
    int w = threadIdx.x >> 5, l = threadIdx.x & 31;
    if (l == 0) { sh_s[w] = s; sh_ss[w] = ss; }
    __syncthreads();
    if (threadIdx.x == 0) {
        float S = 0.f, SS = 0.f;
        #pragma unroll
        for (int i = 0; i < 8; i++) { S += sh_s[i]; SS += sh_ss[i]; }
        float m = S * (1.0f / NP);
        float var = SS * (1.0f / NP) - m * m;
        g_mean[bc] = m;
        g_rstd[bc] = rsqrtf(var + EPSV);
    }
}

// ---------------- out = x + instnorm(g_y) ----------------
__global__ void norm_add_kernel(const float* __restrict__ x) {
    int idx = blockIdx.x * 256 + threadIdx.x;
    int bc = idx >> 12;
    float m = g_mean[bc], r = g_rstd[bc];
    g_out[idx] = x[idx] + (g_y[idx] - m) * r;
}

// ---------------- energy: energy[b,i,j] = sum_c q[b,c,i]*k[b,c,j], K=32 ----------------
__global__ __launch_bounds__(256) void energy_tc() {
    __shared__ float As[8][2][32][4];
    __shared__ float Bs[16][2][32][2];
    int tid = threadIdx.x, b = blockIdx.z;
    int i0 = blockIdx.y * 128, j0 = blockIdx.x * 128;

    int cl = tid >> 4, ig = tid & 15;
    int ckblk = cl >> 3, ckc = cl & 7;

    int wid = tid >> 5, lane = tid & 31;
    int wm = wid & 1, wn = wid >> 1;

    float acc[4][4][4];
    #pragma unroll
    for (int i = 0; i < 4; i++)
        #pragma unroll
        for (int j = 0; j < 4; j++)
            #pragma unroll
            for (int k = 0; k < 4; k++) acc[i][j][k] = 0.f;

    #pragma unroll
    for (int it = 0; it < 2; ++it) {
        int c = it * 16 + cl;
        const float* qsrc = g_q + (size_t)(b * C8 + c) * NP + i0 + ig * 8;
        const float* ksrc = g_k + (size_t)(b * C8 + c) * NP + j0 + ig * 8;
        float4 q0 = *(const float4*)qsrc, q1 = *(const float4*)(qsrc + 4);
        float4 k0 = *(const float4*)ksrc, k1 = *(const float4*)(ksrc + 4);

        __syncthreads();
        {
            float qv[8] = {q0.x, q0.y, q0.z, q0.w, q1.x, q1.y, q1.z, q1.w};
            #pragma unroll
            for (int ii = 0; ii < 8; ii++) {
                int r = ig * 8 + ii;
                int mtile = r >> 4, rr = r & 15;
                As[mtile][ckblk][(rr & 7) * 4 + (ckc & 3)][(rr >> 3) + ((ckc >> 2) << 1)] = tf32r(qv[ii]);
            }
            float kv[8] = {k0.x, k0.y, k0.z, k0.w, k1.x, k1.y, k1.z, k1.w};
            #pragma unroll
            for (int nn = 0; nn < 8; nn++)
                Bs[ig][ckblk][nn * 4 + (ckc & 3)][ckc >> 2] = tf32r(kv[nn]);
        }
        __syncthreads();

        #pragma unroll
        for (int kb = 0; kb < 2; kb++) {
            float4 af[4]; float2 bf[4];
            #pragma unroll
            for (int mt = 0; mt < 4; mt++) af[mt] = *(const float4*)As[wm * 4 + mt][kb][lane];
            #pragma unroll
            for (int nt = 0; nt < 4; nt++) bf[nt] = *(const float2*)Bs[wn * 4 + nt][kb][lane];
            #pragma unroll
            for (int mt = 0; mt < 4; mt++)
                #pragma unroll
                for (int nt = 0; nt < 4; nt++)
                    mma_tf32(acc[mt][nt], af[mt], bf[nt]);
        }
    }

    int g = lane >> 2, tg = lane & 3;
    #pragma unroll
    for (int mt = 0; mt < 4; mt++) {
        int m = i0 + wm * 64 + mt * 16 + g;
        #pragma unroll
        for (int nt = 0; nt < 4; nt++) {
            int n = j0 + wn * 32 + nt * 8 + tg * 2;
            float* d0 = g_attn + ((size_t)b * NP + m) * NP + n;
            *(float2*)d0 = make_float2(acc[mt][nt][0], acc[mt][nt][1]);
            *(float2*)(d0 + (size_t)8 * NP) = make_float2(acc[mt][nt][2], acc[mt][nt][3]);
        }
    }
}

// ---------------- q and k projections fused (FFMA, small) ----------------
__global__ __launch_bounds__(256) void qk_gemm(const float* __restrict__ wq, const float* __restrict__ bq,
                                               const float* __restrict__ wk, const float* __restrict__ bk) {
    __shared__ float As[8][64];
    __shared__ float Bs[8][128];
    int tid = threadIdx.x, b = blockIdx.z;
    int p0 = blockIdx.x * 128;
    int arow = tid >> 2;
    int acol = (tid & 3) * 2;
    const float* ap = ((arow < 32) ? (wq + arow * CC) : (wk + (arow - 32) * CC)) + acol;
    int brow = tid >> 5, bcol = (tid & 31) * 4;
    const float* bp = g_out + (b * CC + brow) * NP + p0 + bcol;
    int ty = tid >> 4, tx = tid & 15;
    float acc[4][8];
    #pragma unroll
    for (int i = 0; i < 4; i++)
        #pragma unroll
        for (int j = 0; j < 8; j++) acc[i][j] = 0.f;

    for (int it = 0; it < CC / 8; ++it) {
        float2 av = *(const float2*)(ap + it * 8);
        float4 bv = *(const float4*)(bp + (size_t)it * 8 * NP);
        __syncthreads();
        As[acol + 0][arow] = av.x;
        As[acol + 1][arow] = av.y;
        *(float4*)&Bs[brow][bcol] = bv;
        __syncthreads();
        #pragma unroll
        for (int kk = 0; kk < 8; kk++) {
            float a[4], bvv[8];
            float4 t0 = *(const float4*)&As[kk][ty * 4];
            a[0]=t0.x; a[1]=t0.y; a[2]=t0.z; a[3]=t0.w;
            float4 u0 = *(const float4*)&Bs[kk][tx * 8];
            float4 u1 = *(const float4*)&Bs[kk][tx * 8 + 4];
            bvv[0]=u0.x; bvv[1]=u0.y; bvv[2]=u0.z; bvv[3]=u0.w;
            bvv[4]=u1.x; bvv[5]=u1.y; bvv[6]=u1.z; bvv[7]=u1.w;
            #pragma unroll
            for (int i = 0; i < 4; i++)
                #pragma unroll
                for (int j = 0; j < 8; j++)
                    acc[i][j] += a[i] * bvv[j];
        }
    }
    #pragma unroll
    for (int i = 0; i < 4; i++) {
        int row = ty * 4 + i;
        float bias = (row < 32) ? bq[row] : bk[row - 32];
        float* dst = ((row < 32) ? (g_q + (b * C8 + row) * NP)
                                 : (g_k + (b * C8 + row - 32) * NP)) + p0 + tx * 8;
        *(float4*)dst       = make_float4(acc[i][0]+bias, acc[i][1]+bias, acc[i][2]+bias, acc[i][3]+bias);
        *(float4*)(dst + 4) = make_float4(acc[i][4]+bias, acc[i][5]+bias, acc[i][6]+bias, acc[i][7]+bias);
    }
}

// ---------------- row softmax over 4096: fp32 in -> bf16 out ----------------
__global__ __launch_bounds__(256) void softmax_kernel() {
    size_t row = blockIdx.x;
    const float* ptr = g_attn + row * (size_t)NP;
    __nv_bfloat16* op = g_attnh + row * (size_t)NP;
    int tid = threadIdx.x;
    float vals[16];
    float m = -1e30f;
    #pragma unroll
    for (int s = 0; s < 16; s++) {
        vals[s] = ptr[tid + s * 256];
        m = fmaxf(m, vals[s]);
    }
    #pragma unroll
    for (int o = 16; o; o >>= 1) m = fmaxf(m, __shfl_xor_sync(0xffffffffu, m, o));
    __shared__ float shm[8], shs[8];
    int w = tid >> 5, l = tid & 31;
    if (l == 0) shm[w] = m;
    __syncthreads();
    m = fmaxf(fmaxf(fmaxf(shm[0], shm[1]), fmaxf(shm[2], shm[3])),
              fmaxf(fmaxf(shm[4], shm[5]), fmaxf(shm[6], shm[7])));
    float sum = 0.f;
    #pragma unroll
    for (int s = 0; s < 16; s++) {
        vals[s] = __expf(vals[s] - m);
        sum += vals[s];
    }
    #pragma unroll
    for (int o = 16; o; o >>= 1) sum += __shfl_xor_sync(0xffffffffu, sum, o);
    if (l == 0) shs[w] = sum;
    __syncthreads();
    sum = shs[0] + shs[1] + shs[2] + shs[3] + shs[4] + shs[5] + shs[6] + shs[7];
    float inv = 1.0f / sum;
    #pragma unroll
    for (int s = 0; s < 16; s++)
        op[tid + s * 256] = __float2bfloat16_rn(vals[s] * inv);
}

// ---------------- launcher ----------------
extern "C" void kernel_launch(void* const* d_in, const int* in_sizes, int n_in,
                              void* d_out, int out_size) {
    const float* x     = (const float*)d_in[0];
    const float* w1    = (const float*)d_in[1];
    const float* b1    = (const float*)d_in[2];
    const float* w2    = (const float*)d_in[3];
    const float* b2    = (const float*)d_in[4];
    const float* wq    = (const float*)d_in[5];
    const float* bq    = (const float*)d_in[6];
    const float* wk    = (const float*)d_in[7];
    const float* bk    = (const float*)d_in[8];
    const float* wv    = (const float*)d_in[9];
    const float* bv    = (const float*)d_in[10];
    const float* gamma = (const float*)d_in[11];
    float* out = (float*)d_out;

    cudaFuncSetAttribute(tc_gemm<0, KCONV>, cudaFuncAttributeMaxDynamicSharedMemorySize, SMEM_DYN);
    cudaFuncSetAttribute(tc_gemm<1, CC>,    cudaFuncAttributeMaxDynamicSharedMemorySize, SMEM_DYN);
    cudaFuncSetAttribute(o_gemm_bf16,       cudaFuncAttributeMaxDynamicSharedMemorySize, OSMEM);

    dim3 g128(NP / 128, CC / 128, BB);   // (32,2,2)

    // conv block (R5 structure: pad kernel pre-materializes padded/normed input)
    pad_kernel<<<BB * CC, 256>>>(x, 0);
    wtrans_kernel<<<CC, 256>>>(w1);
    tc_gemm<0, KCONV><<<g128, 256, SMEM_DYN>>>(nullptr, b1);
    stats_kernel<<<BB * CC, 256>>>();
    pad_kernel<<<BB * CC, 256>>>(nullptr, 1);      // instnorm + relu + pad
    wtrans_kernel<<<CC, 256>>>(w2);
    tc_gemm<0, KCONV><<<g128, 256, SMEM_DYN>>>(nullptr, b2);
    stats_kernel<<<BB * CC, 256>>>();
    norm_add_kernel<<<BB * CC * NP / 256, 256>>>(x);

    // attention
    qk_gemm<<<dim3(NP / 128, 1, BB), 256>>>(wq, bq, wk, bk);
    tc_gemm<1, CC><<<g128, 256, SMEM_DYN>>>(wv, bv);
    energy_tc<<<dim3(NP / 128, NP / 128, BB), 256>>>();
    softmax_kernel<<<BB * NP, 256>>>();
    o_gemm_bf16<<<g128, 256, OSMEM>>>(gamma, out);
}